// round 13
// baseline (speedup 1.0000x reference)
#include <cuda_runtime.h>
#include <cuda_bf16.h>
#include <math.h>
#include <stdint.h>

// ---------------------------------------------------------------------------
// Problem constants
// ---------------------------------------------------------------------------
constexpr int kB     = 16;
constexpr int kH     = 32;
constexpr int kW     = 32;
constexpr int kC     = 384;
constexpr int kDI    = 768;
constexpr int kDTR   = 24;
constexpr int kHID   = 1536;
constexpr int kL     = kH * kW;          // 1024
constexpr int kNTOK  = kB * kL;          // 16384
constexpr int kXPK   = kDTR + 2;         // 26
constexpr int kCH    = 128;              // scan chunk length
constexpr int kNCH   = kL / kCH;         // 8 chunks per sequence

// ---------------------------------------------------------------------------
// Scratch
// ---------------------------------------------------------------------------
__device__ __nv_bfloat16 g_h1  [(size_t)kNTOK * kC];      // bf16 GEMM inputs
__device__ __nv_bfloat16 g_gate[(size_t)kNTOK * kDI];
__device__ __nv_bfloat16 g_h2  [(size_t)kNTOK * kC];
__device__ __nv_bfloat16 g_hid [(size_t)kNTOK * kHID];
__device__ float g_xz  [(size_t)kNTOK * 2 * kDI];
__device__ float g_u   [(size_t)kNTOK * kDI];
__device__ float g_dtbc[(size_t)kNTOK * kXPK];
__device__ float g_xres[(size_t)kNTOK * kC];
// chunked-scan state
__device__ float g_P  [(size_t)kB * kNCH * kDI];
__device__ float g_Q  [(size_t)kB * kNCH * kDI];
__device__ float g_h0 [(size_t)kB * kNCH * kDI];
// transposed weights ([N,K], bf16)
__device__ __nv_bfloat16 g_wt_in [(size_t)(2 * kDI) * kC];
__device__ __nv_bfloat16 g_wt_out[(size_t)kC * kDI];
__device__ __nv_bfloat16 g_wt_f1 [(size_t)kHID * kC];
__device__ __nv_bfloat16 g_wt_f2 [(size_t)kC * kHID];

// ---------------------------------------------------------------------------
// Math helpers
// ---------------------------------------------------------------------------
__device__ __forceinline__ float siluf(float x) {
    return __fdividef(x, 1.f + __expf(-x));
}
__device__ __forceinline__ float gelu_tanh(float x) {
    float x3 = x * x * x;
    float targ = 0.7978845608028654f * (x + 0.044715f * x3);
    float th;
    asm("tanh.approx.f32 %0, %1;" : "=f"(th) : "f"(targ));
    return 0.5f * x * (1.f + th);
}

// ---------------------------------------------------------------------------
// PTX helpers (sm_80-safe: cp.async + mma.sync + ldmatrix)
// ---------------------------------------------------------------------------
__device__ __forceinline__ uint32_t smem_to_u32(const void* p) {
    uint32_t a;
    asm("{ .reg .u64 t; cvta.to.shared.u64 t, %1; cvt.u32.u64 %0, t; }" : "=r"(a) : "l"(p));
    return a;
}
__device__ __forceinline__ void cp_async16(uint32_t sa, const void* g) {
    asm volatile("cp.async.cg.shared.global [%0], [%1], 16;" :: "r"(sa), "l"(g));
}
__device__ __forceinline__ void cp_commit() { asm volatile("cp.async.commit_group;" ::: "memory"); }
template <int N>
__device__ __forceinline__ void cp_wait() { asm volatile("cp.async.wait_group %0;" :: "n"(N) : "memory"); }

__device__ __forceinline__ void ldsm_x4(uint32_t& r0, uint32_t& r1, uint32_t& r2,
                                        uint32_t& r3, uint32_t addr) {
    asm volatile("ldmatrix.sync.aligned.m8n8.x4.shared.b16 {%0,%1,%2,%3}, [%4];"
                 : "=r"(r0), "=r"(r1), "=r"(r2), "=r"(r3) : "r"(addr));
}
__device__ __forceinline__ void mma_bf16(float* c, const uint32_t* a, const uint32_t* b) {
    asm volatile(
        "mma.sync.aligned.m16n8k16.row.col.f32.bf16.bf16.f32 "
        "{%0,%1,%2,%3}, {%4,%5,%6,%7}, {%8,%9}, {%0,%1,%2,%3};"
        : "+f"(c[0]), "+f"(c[1]), "+f"(c[2]), "+f"(c[3])
        : "r"(a[0]), "r"(a[1]), "r"(a[2]), "r"(a[3]), "r"(b[0]), "r"(b[1]));
}

// ---------------------------------------------------------------------------
// bf16 mma.sync GEMM: C[M,N] = A[M,K] @ Bt[N,K]^T  (+ fused epilogue)
//   EPI: 0=store f32  1=+resid f32  2=+bias->gelu->bf16  3=+bias+resid f32
//   BM in {128,64}, BN=128, BK=64 (bf16), BKP=72, DEPTH=3, 256 threads.
// ---------------------------------------------------------------------------
template <int EPI, int BM, int BN>
__global__ __launch_bounds__(256, 2) void mma_gemm(
    const __nv_bfloat16* __restrict__ A, const __nv_bfloat16* __restrict__ Bt,
    void* __restrict__ Cv, int M, int N, int K,
    const float* __restrict__ bias, const float* __restrict__ resid)
{
    constexpr int BK = 64, BKP = 72, DEPTH = 3;      // elements (bf16)
    constexpr int MI = BM / 32;
    constexpr int NJ = BN / 32;
    constexpr int WM = BM / 2;
    constexpr int WN = BN / 4;
    constexpr int A_ELEMS = BM * BKP;
    constexpr int B_ELEMS = BN * BKP;
    constexpr int TPR_A = 256 / BM;
    constexpr int SEG_A = 8 / TPR_A;
    constexpr int TPR_B = 256 / BN;
    constexpr int SEG_B = 8 / TPR_B;

    extern __shared__ __nv_bfloat16 smb[];
    __nv_bfloat16* sA = smb;
    __nv_bfloat16* sB = smb + DEPTH * A_ELEMS;
    const uint32_t sAu = smem_to_u32(sA);
    const uint32_t sBu = smem_to_u32(sB);

    const int tid  = threadIdx.x;
    const int wid  = tid >> 5, lane = tid & 31;
    const int grp  = lane >> 2, tg = lane & 3;
    const int m_w  = (wid & 1) * WM;
    const int n_w  = (wid >> 1) * WN;
    const int tile_m = blockIdx.y * BM;
    const int tile_n = blockIdx.x * BN;

    const int nst = K / BK;
    const int ld_row_a = tid / TPR_A;
    const int ld_sb_a  = (tid % TPR_A) * SEG_A;
    const int ld_row_b = tid / TPR_B;
    const int ld_sb_b  = (tid % TPR_B) * SEG_B;

    const int q  = lane >> 3;
    const int rr = lane & 7;
    const uint32_t aoff = (uint32_t)(((m_w + (q & 1) * 8 + rr) * BKP + (q >> 1) * 8) * 2);
    const uint32_t boff = (uint32_t)(((n_w + (q >> 1) * 8 + rr) * BKP + (q & 1) * 8) * 2);

    auto load_stage = [&](int s) {
        const int slot = s % DEPTH;
        const int k0 = s * BK;
        const __nv_bfloat16* ap = A + (size_t)(tile_m + ld_row_a) * K + k0;
        const uint32_t da = sAu + (uint32_t)(slot * A_ELEMS + ld_row_a * BKP) * 2u;
#pragma unroll
        for (int p = 0; p < SEG_A; p++) {
            const int seg = ld_sb_a + p;
            cp_async16(da + (uint32_t)(seg * 16), ap + seg * 8);
        }
        const __nv_bfloat16* bp = Bt + (size_t)(tile_n + ld_row_b) * K + k0;
        const uint32_t db = sBu + (uint32_t)(slot * B_ELEMS + ld_row_b * BKP) * 2u;
#pragma unroll
        for (int p = 0; p < SEG_B; p++) {
            const int seg = ld_sb_b + p;
            cp_async16(db + (uint32_t)(seg * 16), bp + seg * 8);
        }
        cp_commit();
    };

    float acc[MI][NJ][4];
#pragma unroll
    for (int i = 0; i < MI; i++)
#pragma unroll
        for (int j = 0; j < NJ; j++)
#pragma unroll
            for (int r = 0; r < 4; r++) acc[i][j][r] = 0.f;

    const int pre = (nst < DEPTH - 1) ? nst : (DEPTH - 1);
    for (int s = 0; s < pre; s++) load_stage(s);

    for (int s = 0; s < nst; s++) {
        if (s + DEPTH - 1 < nst) cp_wait<DEPTH - 2>();
        else                     cp_wait<0>();
        __syncthreads();

        const int nxt = s + DEPTH - 1;
        if (nxt < nst) load_stage(nxt);

        const int slot = s % DEPTH;
        const uint32_t aBase = sAu + (uint32_t)(slot * A_ELEMS) * 2u + aoff;
        const uint32_t bBase = sBu + (uint32_t)(slot * B_ELEMS) * 2u + boff;

#pragma unroll
        for (int kk = 0; kk < 4; kk++) {             // 4 x k16 per BK=64
            uint32_t af[MI][4];
#pragma unroll
            for (int i = 0; i < MI; i++)
                ldsm_x4(af[i][0], af[i][1], af[i][2], af[i][3],
                        aBase + (uint32_t)((i * 16 * BKP + kk * 16) * 2));
            uint32_t bf[NJ][2];
#pragma unroll
            for (int jp = 0; jp < NJ / 2; jp++)
                ldsm_x4(bf[2 * jp][0], bf[2 * jp][1], bf[2 * jp + 1][0], bf[2 * jp + 1][1],
                        bBase + (uint32_t)((jp * 16 * BKP + kk * 16) * 2));
#pragma unroll
            for (int i = 0; i < MI; i++)
#pragma unroll
                for (int j = 0; j < NJ; j++)
                    mma_bf16(acc[i][j], af[i], bf[j]);
        }
    }

    // ---- Epilogue ----
    float* Cf = reinterpret_cast<float*>(Cv);
    __nv_bfloat16* Cb = reinterpret_cast<__nv_bfloat16*>(Cv);
#pragma unroll
    for (int i = 0; i < MI; i++) {
        const int rg0 = tile_m + m_w + i * 16 + grp;
#pragma unroll
        for (int j = 0; j < NJ; j++) {
            const int cg = tile_n + n_w + j * 8 + tg * 2;
#pragma unroll
            for (int h = 0; h < 2; h++) {
                const int rg = rg0 + h * 8;
                float2 v = make_float2(acc[i][j][h * 2], acc[i][j][h * 2 + 1]);
                const size_t off = (size_t)rg * N + cg;
                if (EPI == 0) {
                    *reinterpret_cast<float2*>(Cf + off) = v;
                }
                if (EPI == 1) {
                    float2 rr2 = *reinterpret_cast<const float2*>(resid + off);
                    v.x += rr2.x; v.y += rr2.y;
                    *reinterpret_cast<float2*>(Cf + off) = v;
                }
                if (EPI == 2) {
                    float2 bb = *reinterpret_cast<const float2*>(bias + cg);
                    __nv_bfloat162 p;
                    p.x = __float2bfloat16_rn(gelu_tanh(v.x + bb.x));
                    p.y = __float2bfloat16_rn(gelu_tanh(v.y + bb.y));
                    *reinterpret_cast<__nv_bfloat162*>(Cb + off) = p;
                }
                if (EPI == 3) {
                    float2 bb = *reinterpret_cast<const float2*>(bias + cg);
                    float2 rr2 = *reinterpret_cast<const float2*>(resid + off);
                    v.x += bb.x + rr2.x; v.y += bb.y + rr2.y;
                    *reinterpret_cast<float2*>(Cf + off) = v;
                }
            }
        }
    }
}

// ---------------------------------------------------------------------------
// Fused transpose of all 4 weight matrices -> bf16 [N,K]
// ---------------------------------------------------------------------------
__global__ void transpose_all_kernel(
    const float* __restrict__ w_in, const float* __restrict__ w_out,
    const float* __restrict__ fc1,  const float* __restrict__ fc2,
    __nv_bfloat16* __restrict__ o_in, __nv_bfloat16* __restrict__ o_out,
    __nv_bfloat16* __restrict__ o_f1, __nv_bfloat16* __restrict__ o_f2)
{
    __shared__ float t[32][33];
    const int bid = blockIdx.x;
    const float* in; __nv_bfloat16* out; int K, N, tix;
    if (bid < 576)       { in = w_in;  out = o_in;  K = kC;   N = 2 * kDI; tix = bid; }
    else if (bid < 864)  { in = w_out; out = o_out; K = kDI;  N = kC;      tix = bid - 576; }
    else if (bid < 1440) { in = fc1;   out = o_f1;  K = kC;   N = kHID;    tix = bid - 864; }
    else                 { in = fc2;   out = o_f2;  K = kHID; N = kC;      tix = bid - 1440; }
    const int ntx = N / 32;
    const int n0 = (tix % ntx) * 32, k0 = (tix / ntx) * 32;
    const int x = threadIdx.x, y = threadIdx.y;
#pragma unroll
    for (int i = y; i < 32; i += 8)
        t[i][x] = in[(size_t)(k0 + i) * N + n0 + x];
    __syncthreads();
#pragma unroll
    for (int i = y; i < 32; i += 8)
        out[(size_t)(n0 + i) * K + k0 + x] = __float2bfloat16_rn(t[x][i]);
}

// ---------------------------------------------------------------------------
// LayerNorm -> bf16 (used for h1, h2)
// ---------------------------------------------------------------------------
template <int CH, int TPB>
__global__ __launch_bounds__(TPB) void ln_kernel(
    const float* __restrict__ in,
    const float* __restrict__ gam, const float* __restrict__ bet,
    __nv_bfloat16* __restrict__ out, float eps)
{
    constexpr int PER = CH / TPB;
    const int n = blockIdx.x;
    const float* row = in + (size_t)n * CH;

    float v[PER];
    float s = 0.f, s2 = 0.f;
#pragma unroll
    for (int i = 0; i < PER; i++) {
        float t = row[i * TPB + threadIdx.x];
        v[i] = t; s += t; s2 += t * t;
    }
    __shared__ float sm[2 * (TPB / 32)];
#pragma unroll
    for (int o = 16; o; o >>= 1) {
        s  += __shfl_down_sync(0xffffffffu, s,  o);
        s2 += __shfl_down_sync(0xffffffffu, s2, o);
    }
    const int wid = threadIdx.x >> 5, lid = threadIdx.x & 31;
    if (lid == 0) { sm[wid] = s; sm[TPB / 32 + wid] = s2; }
    __syncthreads();
    if (threadIdx.x == 0) {
        float a = 0.f, b = 0.f;
#pragma unroll
        for (int i = 0; i < TPB / 32; i++) { a += sm[i]; b += sm[TPB / 32 + i]; }
        sm[0] = a; sm[1] = b;
    }
    __syncthreads();
    const float mu  = sm[0] * (1.f / CH);
    const float var = sm[1] * (1.f / CH) - mu * mu;
    const float inv = rsqrtf(var + eps);
#pragma unroll
    for (int i = 0; i < PER; i++) {
        const int c = i * TPB + threadIdx.x;
        float o = (v[i] - mu) * inv * gam[c] + bet[c];
        out[(size_t)n * CH + c] = __float2bfloat16_rn(o);
    }
}

// ---------------------------------------------------------------------------
// Depthwise 3x3 SAME conv + silu (4 w-positions x 4 channels per thread)
// ---------------------------------------------------------------------------
__global__ __launch_bounds__(256) void conv_silu_kernel(
    const float* __restrict__ xz, const float* __restrict__ cw,
    float* __restrict__ u)
{
    constexpr int D4 = kDI / 4;   // 192
    __shared__ float4 scwv[9 * D4];
    for (int i = threadIdx.x; i < 9 * D4; i += 256) {
        const int k = i / D4, d4 = i % D4;
        scwv[i] = make_float4(cw[(d4 * 4 + 0) * 9 + k], cw[(d4 * 4 + 1) * 9 + k],
                              cw[(d4 * 4 + 2) * 9 + k], cw[(d4 * 4 + 3) * 9 + k]);
    }
    __syncthreads();

    const int idx = blockIdx.x * 256 + threadIdx.x;
    if (idx >= (kNTOK / 4) * D4) return;
    const int d4 = idx % D4;
    const int nq = idx / D4;
    const int n0 = nq * 4;
    const int w0 = n0 % kW;
    const int h  = (n0 / kW) % kH;

    float4 wv[9];
#pragma unroll
    for (int k = 0; k < 9; k++) wv[k] = scwv[k * D4 + d4];

    float4 acc[4];
#pragma unroll
    for (int t = 0; t < 4; t++) acc[t] = make_float4(0.f, 0.f, 0.f, 0.f);

#pragma unroll
    for (int ky = 0; ky < 3; ky++) {
        const int hh = h + ky - 1;
        if (hh < 0 || hh >= kH) continue;
        const int rowbase = n0 + (ky - 1) * kW;
#pragma unroll
        for (int c = -1; c <= 4; c++) {
            const int ww = w0 + c;
            if (ww < 0 || ww >= kW) continue;
            const float4 v = *reinterpret_cast<const float4*>(
                xz + (size_t)(rowbase + c) * (2 * kDI) + d4 * 4);
#pragma unroll
            for (int t = 0; t < 4; t++) {
                const int kx = c - t + 1;
                if (kx < 0 || kx > 2) continue;
                const float4 w9 = wv[ky * 3 + kx];
                acc[t].x = fmaf(w9.x, v.x, acc[t].x);
                acc[t].y = fmaf(w9.y, v.y, acc[t].y);
                acc[t].z = fmaf(w9.z, v.z, acc[t].z);
                acc[t].w = fmaf(w9.w, v.w, acc[t].w);
            }
        }
    }
#pragma unroll
    for (int t = 0; t < 4; t++) {
        float4 o = make_float4(siluf(acc[t].x), siluf(acc[t].y),
                               siluf(acc[t].z), siluf(acc[t].w));
        *reinterpret_cast<float4*>(u + (size_t)(n0 + t) * kDI + d4 * 4) = o;
    }
}

// ---------------------------------------------------------------------------
// x_proj (768 -> 26): 64 tokens per block, 8 tokens per warp.
//   jj-outer / token-inner: one sW load amortized over 8 FMAs.
// ---------------------------------------------------------------------------
__global__ __launch_bounds__(256) void xproj_kernel(
    const float* __restrict__ u, const float* __restrict__ W,
    float* __restrict__ out)
{
    __shared__ float sW[64 * kXPK];
    __shared__ float su[64][65];
    const int warp = threadIdx.x >> 5, lane = threadIdx.x & 31;
    const int nb = blockIdx.x * 64;
    const int tok0 = warp * 8;
    float acc[8] = {0.f, 0.f, 0.f, 0.f, 0.f, 0.f, 0.f, 0.f};

    for (int j0 = 0; j0 < kDI; j0 += 64) {
        for (int i = threadIdx.x; i < 64 * kXPK; i += 256)
            sW[i] = W[j0 * kXPK + i];
        for (int i = threadIdx.x; i < 64 * 64; i += 256) {
            const int r = i >> 6, col = i & 63;
            su[r][col] = u[(size_t)(nb + r) * kDI + j0 + col];
        }
        __syncthreads();

        if (lane < kXPK) {
#pragma unroll 8
            for (int jj = 0; jj < 64; jj++) {
                const float wv = sW[jj * kXPK + lane];
#pragma unroll
                for (int t = 0; t < 8; t++)
                    acc[t] = fmaf(su[tok0 + t][jj], wv, acc[t]);
            }
        }
        __syncthreads();
    }
    if (lane < kXPK) {
#pragma unroll
        for (int t = 0; t < 8; t++)
            out[(size_t)(nb + tok0 + t) * kXPK + lane] = acc[t];
    }
}

// ---------------------------------------------------------------------------
// Chunked selective scan with fused dt_proj (DS=1)
// ---------------------------------------------------------------------------
__device__ __forceinline__ void dt_math(float z, float Ad, float& av, float& dtv) {
    constexpr float L2E = 1.4426950408889634f;
    constexpr float LN2 = 0.6931471805599453f;
    float l;
    if (z > 15.f) l = z * L2E;
    else          l = __log2f(1.f + exp2f(z * L2E));
    dtv = l * LN2;
    av  = exp2f(Ad * l);
}

// Pass 1: per-(b,chunk,d): P = prod(a), Q = chunk scan from h=0
__global__ __launch_bounds__(256) void scan_chunk_kernel(
    const float* __restrict__ dtbc, const float* __restrict__ dtw,
    const float* __restrict__ dtb,  const float* __restrict__ A_log,
    const float* __restrict__ u,
    float* __restrict__ Pp, float* __restrict__ Qq)
{
    __shared__ float sdt[kCH][kXPK];
    const int d = blockIdx.y * 256 + threadIdx.x;
    const int b = blockIdx.x >> 3;
    const int c = blockIdx.x & 7;
    const size_t tokbase = (size_t)b * kL + c * kCH;

    float wreg[kDTR];
#pragma unroll
    for (int j = 0; j < kDTR; j++) wreg[j] = dtw[j * kDI + d];
    const float bias = dtb[d];
    const float Ad   = -__expf(A_log[d]);

    for (int i = threadIdx.x; i < kCH * kXPK; i += 256)
        sdt[i / kXPK][i % kXPK] = dtbc[tokbase * kXPK + i];
    __syncthreads();

    float P = 1.f, Q = 0.f;
#pragma unroll 4
    for (int t = 0; t < kCH; t++) {
        float z = bias;
#pragma unroll
        for (int j = 0; j < kDTR; j++) z = fmaf(sdt[t][j], wreg[j], z);
        float av, dtv;
        dt_math(z, Ad, av, dtv);
        const float buv = dtv * sdt[t][kDTR] * u[(tokbase + t) * kDI + d];
        P *= av;
        Q = fmaf(av, Q, buv);
    }
    const size_t o = (size_t)blockIdx.x * kDI + d;
    Pp[o] = P;
    Qq[o] = Q;
}

// Pass 2: serial prefix over the 8 chunk summaries -> h0 per (b,c,d)
__global__ __launch_bounds__(256) void scan_prefix_kernel(
    const float* __restrict__ Pp, const float* __restrict__ Qq,
    float* __restrict__ h0)
{
    const int idx = blockIdx.x * 256 + threadIdx.x;   // b*kDI + d
    const int b = idx / kDI, d = idx % kDI;
    float h = 0.f;
#pragma unroll
    for (int c = 0; c < kNCH; c++) {
        const size_t o = (size_t)(b * kNCH + c) * kDI + d;
        h0[o] = h;
        h = fmaf(Pp[o], h, Qq[o]);
    }
}

// Pass 3 (FUSED): recompute scan within chunk from h0, then per-token
// outnorm-LN across the 768 channel-threads, gate with silu(z), emit bf16.
// Block = 768 threads (one per d), grid = kB*kNCH = 128 blocks.
__global__ __launch_bounds__(768) void scan_apply_ln_kernel(
    const float* __restrict__ dtbc, const float* __restrict__ dtw,
    const float* __restrict__ dtb,  const float* __restrict__ A_log,
    const float* __restrict__ u,    const float* __restrict__ Dp,
    const float* __restrict__ h0,   const float* __restrict__ xz,
    const float* __restrict__ ong,  const float* __restrict__ onb,
    __nv_bfloat16* __restrict__ gate)
{
    __shared__ float sdt[kCH][kXPK];
    __shared__ float red[2][24];
    __shared__ float stat[2];
    const int d = threadIdx.x;               // 0..767
    const int b = blockIdx.x >> 3;
    const int c = blockIdx.x & 7;
    const size_t tokbase = (size_t)b * kL + c * kCH;
    const int warp = d >> 5, lane = d & 31;

    float wreg[kDTR];
#pragma unroll
    for (int j = 0; j < kDTR; j++) wreg[j] = dtw[j * kDI + d];
    const float bias = dtb[d];
    const float Ad   = -__expf(A_log[d]);
    const float Dd   = Dp[d];
    const float gam  = ong[d];
    const float bet  = onb[d];

    for (int i = threadIdx.x; i < kCH * kXPK; i += 768)
        sdt[i / kXPK][i % kXPK] = dtbc[tokbase * kXPK + i];
    __syncthreads();

    float h = h0[(size_t)blockIdx.x * kDI + d];
    for (int t = 0; t < kCH; t++) {
        float z = bias;
#pragma unroll
        for (int j = 0; j < kDTR; j++) z = fmaf(sdt[t][j], wreg[j], z);
        float av, dtv;
        dt_math(z, Ad, av, dtv);
        const size_t idx = (tokbase + t) * kDI + d;
        const float uv = u[idx];
        h = fmaf(av, h, dtv * sdt[t][kDTR] * uv);
        const float yv = fmaf(h, sdt[t][kDTR + 1], uv * Dd);

        // ---- block LN over the 768 channels of this token ----
        float s1 = yv, s2 = yv * yv;
#pragma unroll
        for (int o = 16; o; o >>= 1) {
            s1 += __shfl_down_sync(0xffffffffu, s1, o);
            s2 += __shfl_down_sync(0xffffffffu, s2, o);
        }
        if (lane == 0) { red[0][warp] = s1; red[1][warp] = s2; }
        __syncthreads();
        if (d < 32) {
            float a = (d < 24) ? red[0][d] : 0.f;
            float q = (d < 24) ? red[1][d] : 0.f;
#pragma unroll
            for (int o = 16; o; o >>= 1) {
                a += __shfl_down_sync(0xffffffffu, a, o);
                q += __shfl_down_sync(0xffffffffu, q, o);
            }
            if (d == 0) {
                const float mu  = a * (1.f / kDI);
                const float var = q * (1.f / kDI) - mu * mu;
                stat[0] = mu;
                stat[1] = rsqrtf(var + 1e-5f);
            }
        }
        __syncthreads();

        const float o  = (yv - stat[0]) * stat[1] * gam + bet;
        const float zv = xz[(tokbase + t) * (2 * kDI) + kDI + d];
        gate[idx] = __float2bfloat16_rn(o * siluf(zv));
    }
}

// ---------------------------------------------------------------------------
// Launch
// ---------------------------------------------------------------------------
extern "C" void kernel_launch(void* const* d_in, const int* in_sizes, int n_in,
                              void* d_out, int out_size)
{
    const float* x         = (const float*)d_in[0];
    const float* ln1_g     = (const float*)d_in[1];
    const float* ln1_b     = (const float*)d_in[2];
    const float* w_in      = (const float*)d_in[3];
    const float* conv_w    = (const float*)d_in[4];
    const float* x_proj_w  = (const float*)d_in[5];
    const float* dt_proj_w = (const float*)d_in[6];
    const float* dt_proj_b = (const float*)d_in[7];
    const float* A_log     = (const float*)d_in[8];
    const float* Dp        = (const float*)d_in[9];
    const float* outnorm_g = (const float*)d_in[10];
    const float* outnorm_b = (const float*)d_in[11];
    const float* w_out     = (const float*)d_in[12];
    const float* ln2_g     = (const float*)d_in[13];
    const float* ln2_b     = (const float*)d_in[14];
    const float* fc1_w     = (const float*)d_in[15];
    const float* fc1_b     = (const float*)d_in[16];
    const float* fc2_w     = (const float*)d_in[17];
    const float* fc2_b     = (const float*)d_in[18];
    float* out = (float*)d_out;

    float *xz, *u, *dtbc, *xres, *Pp, *Qq, *h0;
    __nv_bfloat16 *h1, *gate, *h2, *hid;
    __nv_bfloat16 *wt_in, *wt_out, *wt_f1, *wt_f2;
    cudaGetSymbolAddress((void**)&h1,    g_h1);
    cudaGetSymbolAddress((void**)&xz,    g_xz);
    cudaGetSymbolAddress((void**)&u,     g_u);
    cudaGetSymbolAddress((void**)&dtbc,  g_dtbc);
    cudaGetSymbolAddress((void**)&gate,  g_gate);
    cudaGetSymbolAddress((void**)&xres,  g_xres);
    cudaGetSymbolAddress((void**)&h2,    g_h2);
    cudaGetSymbolAddress((void**)&hid,   g_hid);
    cudaGetSymbolAddress((void**)&Pp,    g_P);
    cudaGetSymbolAddress((void**)&Qq,    g_Q);
    cudaGetSymbolAddress((void**)&h0,    g_h0);
    cudaGetSymbolAddress((void**)&wt_in, g_wt_in);
    cudaGetSymbolAddress((void**)&wt_out,g_wt_out);
    cudaGetSymbolAddress((void**)&wt_f1, g_wt_f1);
    cudaGetSymbolAddress((void**)&wt_f2, g_wt_f2);

    // dynamic smem (bytes): DEPTH(3) * (BM+BN) rows * BKP(72) * 2B
    const int SMEM128 = 3 * (128 + 128) * 72 * 2;   // 110592
    const int SMEM64  = 3 * (64 + 128)  * 72 * 2;   // 82944
    cudaFuncSetAttribute((void*)mma_gemm<0, 128, 128>, cudaFuncAttributeMaxDynamicSharedMemorySize, SMEM128);
    cudaFuncSetAttribute((void*)mma_gemm<2, 128, 128>, cudaFuncAttributeMaxDynamicSharedMemorySize, SMEM128);
    cudaFuncSetAttribute((void*)mma_gemm<1, 64, 128>,  cudaFuncAttributeMaxDynamicSharedMemorySize, SMEM64);
    cudaFuncSetAttribute((void*)mma_gemm<3, 64, 128>,  cudaFuncAttributeMaxDynamicSharedMemorySize, SMEM64);

    // 0) transpose all weights -> bf16 [N,K] (one launch)
    transpose_all_kernel<<<2016, dim3(32, 8)>>>(w_in, w_out, fc1_w, fc2_w,
                                                wt_in, wt_out, wt_f1, wt_f2);

    // 1) h1 = bf16(LN(x))
    ln_kernel<kC, 128><<<kNTOK, 128>>>(x, ln1_g, ln1_b, h1, 1e-6f);

    // 2) xz = h1 @ w_in   (N=1536, fp32 out)
    mma_gemm<0, 128, 128><<<dim3((2 * kDI) / 128, kNTOK / 128), 256, SMEM128>>>(
        h1, wt_in, xz, kNTOK, 2 * kDI, kC, nullptr, nullptr);

    // 3) u = silu(dwconv3x3(xm))   (fp32)
    conv_silu_kernel<<<((kNTOK / 4) * (kDI / 4) + 255) / 256, 256>>>(xz, conv_w, u);

    // 4) dtbc = u @ x_proj_w   (fp32)
    xproj_kernel<<<kNTOK / 64, 256>>>(u, x_proj_w, dtbc);

    // 5) chunked selective scan with fused dt_proj; pass 3 fuses LN+gate
    scan_chunk_kernel<<<dim3(kB * kNCH, kDI / 256), 256>>>(
        dtbc, dt_proj_w, dt_proj_b, A_log, u, Pp, Qq);
    scan_prefix_kernel<<<(kB * kDI) / 256, 256>>>(Pp, Qq, h0);
    scan_apply_ln_kernel<<<kB * kNCH, 768>>>(
        dtbc, dt_proj_w, dt_proj_b, A_log, u, Dp, h0, xz,
        outnorm_g, outnorm_b, gate);

    // 6) xres = gate @ w_out + x   (N=384, BM=64, fp32 out)
    mma_gemm<1, 64, 128><<<dim3(kC / 128, kNTOK / 64), 256, SMEM64>>>(
        gate, wt_out, xres, kNTOK, kC, kDI, nullptr, x);

    // 7) h2 = bf16(LN(xres))
    ln_kernel<kC, 128><<<kNTOK, 128>>>(xres, ln2_g, ln2_b, h2, 1e-6f);

    // 8) hid = bf16(gelu(h2 @ fc1_w + fc1_b))   (N=1536)
    mma_gemm<2, 128, 128><<<dim3(kHID / 128, kNTOK / 128), 256, SMEM128>>>(
        h2, wt_f1, hid, kNTOK, kHID, kC, fc1_b, nullptr);

    // 9) out = hid @ fc2_w + fc2_b + xres   (N=384, BM=64, fp32 out)
    mma_gemm<3, 64, 128><<<dim3(kC / 128, kNTOK / 64), 256, SMEM64>>>(
        hid, wt_f2, out, kNTOK, kC, kHID, fc2_b, xres);
}

// round 14
// speedup vs baseline: 1.2416x; 1.2416x over previous
#include <cuda_runtime.h>
#include <cuda_bf16.h>
#include <math.h>
#include <stdint.h>

// ---------------------------------------------------------------------------
// Problem constants
// ---------------------------------------------------------------------------
constexpr int kB     = 16;
constexpr int kH     = 32;
constexpr int kW     = 32;
constexpr int kC     = 384;
constexpr int kDI    = 768;
constexpr int kDTR   = 24;
constexpr int kHID   = 1536;
constexpr int kL     = kH * kW;          // 1024
constexpr int kNTOK  = kB * kL;          // 16384
constexpr int kXPK   = kDTR + 2;         // 26
constexpr int kCH    = 128;              // scan chunk length
constexpr int kNCH   = kL / kCH;         // 8 chunks per sequence
constexpr int kTT    = 32;               // pass-3 token tile (smem-resident y)

// ---------------------------------------------------------------------------
// Scratch
// ---------------------------------------------------------------------------
__device__ __nv_bfloat16 g_h1  [(size_t)kNTOK * kC];      // bf16 GEMM inputs
__device__ __nv_bfloat16 g_gate[(size_t)kNTOK * kDI];
__device__ __nv_bfloat16 g_h2  [(size_t)kNTOK * kC];
__device__ __nv_bfloat16 g_hid [(size_t)kNTOK * kHID];
__device__ float g_xz  [(size_t)kNTOK * 2 * kDI];
__device__ float g_u   [(size_t)kNTOK * kDI];
__device__ float g_dtbc[(size_t)kNTOK * kXPK];
__device__ float g_xres[(size_t)kNTOK * kC];
// chunked-scan state
__device__ float g_P  [(size_t)kB * kNCH * kDI];
__device__ float g_Q  [(size_t)kB * kNCH * kDI];
__device__ float g_h0 [(size_t)kB * kNCH * kDI];
// transposed weights ([N,K], bf16)
__device__ __nv_bfloat16 g_wt_in [(size_t)(2 * kDI) * kC];
__device__ __nv_bfloat16 g_wt_out[(size_t)kC * kDI];
__device__ __nv_bfloat16 g_wt_f1 [(size_t)kHID * kC];
__device__ __nv_bfloat16 g_wt_f2 [(size_t)kC * kHID];

// ---------------------------------------------------------------------------
// Math helpers
// ---------------------------------------------------------------------------
__device__ __forceinline__ float siluf(float x) {
    return __fdividef(x, 1.f + __expf(-x));
}
__device__ __forceinline__ float gelu_tanh(float x) {
    float x3 = x * x * x;
    float targ = 0.7978845608028654f * (x + 0.044715f * x3);
    float th;
    asm("tanh.approx.f32 %0, %1;" : "=f"(th) : "f"(targ));
    return 0.5f * x * (1.f + th);
}

// ---------------------------------------------------------------------------
// PTX helpers (sm_80-safe: cp.async + mma.sync + ldmatrix)
// ---------------------------------------------------------------------------
__device__ __forceinline__ uint32_t smem_to_u32(const void* p) {
    uint32_t a;
    asm("{ .reg .u64 t; cvta.to.shared.u64 t, %1; cvt.u32.u64 %0, t; }" : "=r"(a) : "l"(p));
    return a;
}
__device__ __forceinline__ void cp_async16(uint32_t sa, const void* g) {
    asm volatile("cp.async.cg.shared.global [%0], [%1], 16;" :: "r"(sa), "l"(g));
}
__device__ __forceinline__ void cp_commit() { asm volatile("cp.async.commit_group;" ::: "memory"); }
template <int N>
__device__ __forceinline__ void cp_wait() { asm volatile("cp.async.wait_group %0;" :: "n"(N) : "memory"); }

__device__ __forceinline__ void ldsm_x4(uint32_t& r0, uint32_t& r1, uint32_t& r2,
                                        uint32_t& r3, uint32_t addr) {
    asm volatile("ldmatrix.sync.aligned.m8n8.x4.shared.b16 {%0,%1,%2,%3}, [%4];"
                 : "=r"(r0), "=r"(r1), "=r"(r2), "=r"(r3) : "r"(addr));
}
__device__ __forceinline__ void mma_bf16(float* c, const uint32_t* a, const uint32_t* b) {
    asm volatile(
        "mma.sync.aligned.m16n8k16.row.col.f32.bf16.bf16.f32 "
        "{%0,%1,%2,%3}, {%4,%5,%6,%7}, {%8,%9}, {%0,%1,%2,%3};"
        : "+f"(c[0]), "+f"(c[1]), "+f"(c[2]), "+f"(c[3])
        : "r"(a[0]), "r"(a[1]), "r"(a[2]), "r"(a[3]), "r"(b[0]), "r"(b[1]));
}

// ---------------------------------------------------------------------------
// bf16 mma.sync GEMM: C[M,N] = A[M,K] @ Bt[N,K]^T  (+ fused epilogue)
//   EPI: 0=store f32  1=+resid f32  2=+bias->gelu->bf16  3=+bias+resid f32
//   BM in {128,64}, BN=128, BK=64 (bf16), BKP=72, DEPTH=3, 256 threads.
// ---------------------------------------------------------------------------
template <int EPI, int BM, int BN>
__global__ __launch_bounds__(256, 2) void mma_gemm(
    const __nv_bfloat16* __restrict__ A, const __nv_bfloat16* __restrict__ Bt,
    void* __restrict__ Cv, int M, int N, int K,
    const float* __restrict__ bias, const float* __restrict__ resid)
{
    constexpr int BK = 64, BKP = 72, DEPTH = 3;      // elements (bf16)
    constexpr int MI = BM / 32;
    constexpr int NJ = BN / 32;
    constexpr int WM = BM / 2;
    constexpr int WN = BN / 4;
    constexpr int A_ELEMS = BM * BKP;
    constexpr int B_ELEMS = BN * BKP;
    constexpr int TPR_A = 256 / BM;
    constexpr int SEG_A = 8 / TPR_A;
    constexpr int TPR_B = 256 / BN;
    constexpr int SEG_B = 8 / TPR_B;

    extern __shared__ __nv_bfloat16 smb[];
    __nv_bfloat16* sA = smb;
    __nv_bfloat16* sB = smb + DEPTH * A_ELEMS;
    const uint32_t sAu = smem_to_u32(sA);
    const uint32_t sBu = smem_to_u32(sB);

    const int tid  = threadIdx.x;
    const int wid  = tid >> 5, lane = tid & 31;
    const int grp  = lane >> 2, tg = lane & 3;
    const int m_w  = (wid & 1) * WM;
    const int n_w  = (wid >> 1) * WN;
    const int tile_m = blockIdx.y * BM;
    const int tile_n = blockIdx.x * BN;

    const int nst = K / BK;
    const int ld_row_a = tid / TPR_A;
    const int ld_sb_a  = (tid % TPR_A) * SEG_A;
    const int ld_row_b = tid / TPR_B;
    const int ld_sb_b  = (tid % TPR_B) * SEG_B;

    const int q  = lane >> 3;
    const int rr = lane & 7;
    const uint32_t aoff = (uint32_t)(((m_w + (q & 1) * 8 + rr) * BKP + (q >> 1) * 8) * 2);
    const uint32_t boff = (uint32_t)(((n_w + (q >> 1) * 8 + rr) * BKP + (q & 1) * 8) * 2);

    auto load_stage = [&](int s) {
        const int slot = s % DEPTH;
        const int k0 = s * BK;
        const __nv_bfloat16* ap = A + (size_t)(tile_m + ld_row_a) * K + k0;
        const uint32_t da = sAu + (uint32_t)(slot * A_ELEMS + ld_row_a * BKP) * 2u;
#pragma unroll
        for (int p = 0; p < SEG_A; p++) {
            const int seg = ld_sb_a + p;
            cp_async16(da + (uint32_t)(seg * 16), ap + seg * 8);
        }
        const __nv_bfloat16* bp = Bt + (size_t)(tile_n + ld_row_b) * K + k0;
        const uint32_t db = sBu + (uint32_t)(slot * B_ELEMS + ld_row_b * BKP) * 2u;
#pragma unroll
        for (int p = 0; p < SEG_B; p++) {
            const int seg = ld_sb_b + p;
            cp_async16(db + (uint32_t)(seg * 16), bp + seg * 8);
        }
        cp_commit();
    };

    float acc[MI][NJ][4];
#pragma unroll
    for (int i = 0; i < MI; i++)
#pragma unroll
        for (int j = 0; j < NJ; j++)
#pragma unroll
            for (int r = 0; r < 4; r++) acc[i][j][r] = 0.f;

    const int pre = (nst < DEPTH - 1) ? nst : (DEPTH - 1);
    for (int s = 0; s < pre; s++) load_stage(s);

    for (int s = 0; s < nst; s++) {
        if (s + DEPTH - 1 < nst) cp_wait<DEPTH - 2>();
        else                     cp_wait<0>();
        __syncthreads();

        const int nxt = s + DEPTH - 1;
        if (nxt < nst) load_stage(nxt);

        const int slot = s % DEPTH;
        const uint32_t aBase = sAu + (uint32_t)(slot * A_ELEMS) * 2u + aoff;
        const uint32_t bBase = sBu + (uint32_t)(slot * B_ELEMS) * 2u + boff;

#pragma unroll
        for (int kk = 0; kk < 4; kk++) {             // 4 x k16 per BK=64
            uint32_t af[MI][4];
#pragma unroll
            for (int i = 0; i < MI; i++)
                ldsm_x4(af[i][0], af[i][1], af[i][2], af[i][3],
                        aBase + (uint32_t)((i * 16 * BKP + kk * 16) * 2));
            uint32_t bf[NJ][2];
#pragma unroll
            for (int jp = 0; jp < NJ / 2; jp++)
                ldsm_x4(bf[2 * jp][0], bf[2 * jp][1], bf[2 * jp + 1][0], bf[2 * jp + 1][1],
                        bBase + (uint32_t)((jp * 16 * BKP + kk * 16) * 2));
#pragma unroll
            for (int i = 0; i < MI; i++)
#pragma unroll
                for (int j = 0; j < NJ; j++)
                    mma_bf16(acc[i][j], af[i], bf[j]);
        }
    }

    // ---- Epilogue ----
    float* Cf = reinterpret_cast<float*>(Cv);
    __nv_bfloat16* Cb = reinterpret_cast<__nv_bfloat16*>(Cv);
#pragma unroll
    for (int i = 0; i < MI; i++) {
        const int rg0 = tile_m + m_w + i * 16 + grp;
#pragma unroll
        for (int j = 0; j < NJ; j++) {
            const int cg = tile_n + n_w + j * 8 + tg * 2;
#pragma unroll
            for (int h = 0; h < 2; h++) {
                const int rg = rg0 + h * 8;
                float2 v = make_float2(acc[i][j][h * 2], acc[i][j][h * 2 + 1]);
                const size_t off = (size_t)rg * N + cg;
                if (EPI == 0) {
                    *reinterpret_cast<float2*>(Cf + off) = v;
                }
                if (EPI == 1) {
                    float2 rr2 = *reinterpret_cast<const float2*>(resid + off);
                    v.x += rr2.x; v.y += rr2.y;
                    *reinterpret_cast<float2*>(Cf + off) = v;
                }
                if (EPI == 2) {
                    float2 bb = *reinterpret_cast<const float2*>(bias + cg);
                    __nv_bfloat162 p;
                    p.x = __float2bfloat16_rn(gelu_tanh(v.x + bb.x));
                    p.y = __float2bfloat16_rn(gelu_tanh(v.y + bb.y));
                    *reinterpret_cast<__nv_bfloat162*>(Cb + off) = p;
                }
                if (EPI == 3) {
                    float2 bb = *reinterpret_cast<const float2*>(bias + cg);
                    float2 rr2 = *reinterpret_cast<const float2*>(resid + off);
                    v.x += bb.x + rr2.x; v.y += bb.y + rr2.y;
                    *reinterpret_cast<float2*>(Cf + off) = v;
                }
            }
        }
    }
}

// ---------------------------------------------------------------------------
// Fused transpose of all 4 weight matrices -> bf16 [N,K]
// ---------------------------------------------------------------------------
__global__ void transpose_all_kernel(
    const float* __restrict__ w_in, const float* __restrict__ w_out,
    const float* __restrict__ fc1,  const float* __restrict__ fc2,
    __nv_bfloat16* __restrict__ o_in, __nv_bfloat16* __restrict__ o_out,
    __nv_bfloat16* __restrict__ o_f1, __nv_bfloat16* __restrict__ o_f2)
{
    __shared__ float t[32][33];
    const int bid = blockIdx.x;
    const float* in; __nv_bfloat16* out; int K, N, tix;
    if (bid < 576)       { in = w_in;  out = o_in;  K = kC;   N = 2 * kDI; tix = bid; }
    else if (bid < 864)  { in = w_out; out = o_out; K = kDI;  N = kC;      tix = bid - 576; }
    else if (bid < 1440) { in = fc1;   out = o_f1;  K = kC;   N = kHID;    tix = bid - 864; }
    else                 { in = fc2;   out = o_f2;  K = kHID; N = kC;      tix = bid - 1440; }
    const int ntx = N / 32;
    const int n0 = (tix % ntx) * 32, k0 = (tix / ntx) * 32;
    const int x = threadIdx.x, y = threadIdx.y;
#pragma unroll
    for (int i = y; i < 32; i += 8)
        t[i][x] = in[(size_t)(k0 + i) * N + n0 + x];
    __syncthreads();
#pragma unroll
    for (int i = y; i < 32; i += 8)
        out[(size_t)(n0 + i) * K + k0 + x] = __float2bfloat16_rn(t[x][i]);
}

// ---------------------------------------------------------------------------
// LayerNorm -> bf16 (used for h1, h2)
// ---------------------------------------------------------------------------
template <int CH, int TPB>
__global__ __launch_bounds__(TPB) void ln_kernel(
    const float* __restrict__ in,
    const float* __restrict__ gam, const float* __restrict__ bet,
    __nv_bfloat16* __restrict__ out, float eps)
{
    constexpr int PER = CH / TPB;
    const int n = blockIdx.x;
    const float* row = in + (size_t)n * CH;

    float v[PER];
    float s = 0.f, s2 = 0.f;
#pragma unroll
    for (int i = 0; i < PER; i++) {
        float t = row[i * TPB + threadIdx.x];
        v[i] = t; s += t; s2 += t * t;
    }
    __shared__ float sm[2 * (TPB / 32)];
#pragma unroll
    for (int o = 16; o; o >>= 1) {
        s  += __shfl_down_sync(0xffffffffu, s,  o);
        s2 += __shfl_down_sync(0xffffffffu, s2, o);
    }
    const int wid = threadIdx.x >> 5, lid = threadIdx.x & 31;
    if (lid == 0) { sm[wid] = s; sm[TPB / 32 + wid] = s2; }
    __syncthreads();
    if (threadIdx.x == 0) {
        float a = 0.f, b = 0.f;
#pragma unroll
        for (int i = 0; i < TPB / 32; i++) { a += sm[i]; b += sm[TPB / 32 + i]; }
        sm[0] = a; sm[1] = b;
    }
    __syncthreads();
    const float mu  = sm[0] * (1.f / CH);
    const float var = sm[1] * (1.f / CH) - mu * mu;
    const float inv = rsqrtf(var + eps);
#pragma unroll
    for (int i = 0; i < PER; i++) {
        const int c = i * TPB + threadIdx.x;
        float o = (v[i] - mu) * inv * gam[c] + bet[c];
        out[(size_t)n * CH + c] = __float2bfloat16_rn(o);
    }
}

// ---------------------------------------------------------------------------
// Depthwise 3x3 SAME conv + silu (4 w-positions x 4 channels per thread)
// ---------------------------------------------------------------------------
__global__ __launch_bounds__(256) void conv_silu_kernel(
    const float* __restrict__ xz, const float* __restrict__ cw,
    float* __restrict__ u)
{
    constexpr int D4 = kDI / 4;   // 192
    __shared__ float4 scwv[9 * D4];
    for (int i = threadIdx.x; i < 9 * D4; i += 256) {
        const int k = i / D4, d4 = i % D4;
        scwv[i] = make_float4(cw[(d4 * 4 + 0) * 9 + k], cw[(d4 * 4 + 1) * 9 + k],
                              cw[(d4 * 4 + 2) * 9 + k], cw[(d4 * 4 + 3) * 9 + k]);
    }
    __syncthreads();

    const int idx = blockIdx.x * 256 + threadIdx.x;
    if (idx >= (kNTOK / 4) * D4) return;
    const int d4 = idx % D4;
    const int nq = idx / D4;
    const int n0 = nq * 4;
    const int w0 = n0 % kW;
    const int h  = (n0 / kW) % kH;

    float4 wv[9];
#pragma unroll
    for (int k = 0; k < 9; k++) wv[k] = scwv[k * D4 + d4];

    float4 acc[4];
#pragma unroll
    for (int t = 0; t < 4; t++) acc[t] = make_float4(0.f, 0.f, 0.f, 0.f);

#pragma unroll
    for (int ky = 0; ky < 3; ky++) {
        const int hh = h + ky - 1;
        if (hh < 0 || hh >= kH) continue;
        const int rowbase = n0 + (ky - 1) * kW;
#pragma unroll
        for (int c = -1; c <= 4; c++) {
            const int ww = w0 + c;
            if (ww < 0 || ww >= kW) continue;
            const float4 v = *reinterpret_cast<const float4*>(
                xz + (size_t)(rowbase + c) * (2 * kDI) + d4 * 4);
#pragma unroll
            for (int t = 0; t < 4; t++) {
                const int kx = c - t + 1;
                if (kx < 0 || kx > 2) continue;
                const float4 w9 = wv[ky * 3 + kx];
                acc[t].x = fmaf(w9.x, v.x, acc[t].x);
                acc[t].y = fmaf(w9.y, v.y, acc[t].y);
                acc[t].z = fmaf(w9.z, v.z, acc[t].z);
                acc[t].w = fmaf(w9.w, v.w, acc[t].w);
            }
        }
    }
#pragma unroll
    for (int t = 0; t < 4; t++) {
        float4 o = make_float4(siluf(acc[t].x), siluf(acc[t].y),
                               siluf(acc[t].z), siluf(acc[t].w));
        *reinterpret_cast<float4*>(u + (size_t)(n0 + t) * kDI + d4 * 4) = o;
    }
}

// ---------------------------------------------------------------------------
// x_proj (768 -> 26): 64 tokens per block, 8 tokens per warp (jj-outer)
// ---------------------------------------------------------------------------
__global__ __launch_bounds__(256) void xproj_kernel(
    const float* __restrict__ u, const float* __restrict__ W,
    float* __restrict__ out)
{
    __shared__ float sW[64 * kXPK];
    __shared__ float su[64][65];
    const int warp = threadIdx.x >> 5, lane = threadIdx.x & 31;
    const int nb = blockIdx.x * 64;
    const int tok0 = warp * 8;
    float acc[8] = {0.f, 0.f, 0.f, 0.f, 0.f, 0.f, 0.f, 0.f};

    for (int j0 = 0; j0 < kDI; j0 += 64) {
        for (int i = threadIdx.x; i < 64 * kXPK; i += 256)
            sW[i] = W[j0 * kXPK + i];
        for (int i = threadIdx.x; i < 64 * 64; i += 256) {
            const int r = i >> 6, col = i & 63;
            su[r][col] = u[(size_t)(nb + r) * kDI + j0 + col];
        }
        __syncthreads();

        if (lane < kXPK) {
#pragma unroll 8
            for (int jj = 0; jj < 64; jj++) {
                const float wv = sW[jj * kXPK + lane];
#pragma unroll
                for (int t = 0; t < 8; t++)
                    acc[t] = fmaf(su[tok0 + t][jj], wv, acc[t]);
            }
        }
        __syncthreads();
    }
    if (lane < kXPK) {
#pragma unroll
        for (int t = 0; t < 8; t++)
            out[(size_t)(nb + tok0 + t) * kXPK + lane] = acc[t];
    }
}

// ---------------------------------------------------------------------------
// Chunked selective scan with fused dt_proj (DS=1)
// ---------------------------------------------------------------------------
__device__ __forceinline__ void dt_math(float z, float Ad, float& av, float& dtv) {
    constexpr float L2E = 1.4426950408889634f;
    constexpr float LN2 = 0.6931471805599453f;
    float l;
    if (z > 15.f) l = z * L2E;
    else          l = __log2f(1.f + exp2f(z * L2E));
    dtv = l * LN2;
    av  = exp2f(Ad * l);
}

// Pass 1: per-(b,chunk,d): P = prod(a), Q = chunk scan from h=0
__global__ __launch_bounds__(256) void scan_chunk_kernel(
    const float* __restrict__ dtbc, const float* __restrict__ dtw,
    const float* __restrict__ dtb,  const float* __restrict__ A_log,
    const float* __restrict__ u,
    float* __restrict__ Pp, float* __restrict__ Qq)
{
    __shared__ float sdt[kCH][kXPK];
    const int d = blockIdx.y * 256 + threadIdx.x;
    const int b = blockIdx.x >> 3;
    const int c = blockIdx.x & 7;
    const size_t tokbase = (size_t)b * kL + c * kCH;

    float wreg[kDTR];
#pragma unroll
    for (int j = 0; j < kDTR; j++) wreg[j] = dtw[j * kDI + d];
    const float bias = dtb[d];
    const float Ad   = -__expf(A_log[d]);

    for (int i = threadIdx.x; i < kCH * kXPK; i += 256)
        sdt[i / kXPK][i % kXPK] = dtbc[tokbase * kXPK + i];
    __syncthreads();

    float P = 1.f, Q = 0.f;
#pragma unroll 4
    for (int t = 0; t < kCH; t++) {
        float z = bias;
#pragma unroll
        for (int j = 0; j < kDTR; j++) z = fmaf(sdt[t][j], wreg[j], z);
        float av, dtv;
        dt_math(z, Ad, av, dtv);
        const float buv = dtv * sdt[t][kDTR] * u[(tokbase + t) * kDI + d];
        P *= av;
        Q = fmaf(av, Q, buv);
    }
    const size_t o = (size_t)blockIdx.x * kDI + d;
    Pp[o] = P;
    Qq[o] = Q;
}

// Pass 2: serial prefix over the 8 chunk summaries -> h0 per (b,c,d)
__global__ __launch_bounds__(256) void scan_prefix_kernel(
    const float* __restrict__ Pp, const float* __restrict__ Qq,
    float* __restrict__ h0)
{
    const int idx = blockIdx.x * 256 + threadIdx.x;   // b*kDI + d
    const int b = idx / kDI, d = idx % kDI;
    float h = 0.f;
#pragma unroll
    for (int c = 0; c < kNCH; c++) {
        const size_t o = (size_t)(b * kNCH + c) * kDI + d;
        h0[o] = h;
        h = fmaf(Pp[o], h, Qq[o]);
    }
}

// Pass 3 (FUSED, tiled): scan 32 tokens barrier-free into an smem y-tile,
// then warp-per-token LN + silu(z) gate -> bf16. Two barriers per 32 tokens,
// so u-load pipelining inside phase A is preserved.
// Block = 768 threads (one per channel), grid = kB*kNCH = 128 blocks.
__global__ __launch_bounds__(768, 1) void scan_apply_ln_kernel(
    const float* __restrict__ dtbc, const float* __restrict__ dtw,
    const float* __restrict__ dtb,  const float* __restrict__ A_log,
    const float* __restrict__ u,    const float* __restrict__ Dp,
    const float* __restrict__ h0,   const float* __restrict__ xz,
    const float* __restrict__ ong,  const float* __restrict__ onb,
    __nv_bfloat16* __restrict__ gate)
{
    extern __shared__ float smf[];
    float* sy   = smf;                      // [kTT][kDI]
    float* sdt  = smf + kTT * kDI;          // [kCH][kXPK]
    float* sgam = sdt + kCH * kXPK;         // [kDI]
    float* sbet = sgam + kDI;               // [kDI]

    const int d = threadIdx.x;              // 0..767
    const int b = blockIdx.x >> 3;
    const int c = blockIdx.x & 7;
    const size_t tokbase = (size_t)b * kL + c * kCH;
    const int warp = d >> 5, lane = d & 31;

    float wreg[kDTR];
#pragma unroll
    for (int j = 0; j < kDTR; j++) wreg[j] = dtw[j * kDI + d];
    const float bias = dtb[d];
    const float Ad   = -__expf(A_log[d]);
    const float Dd   = Dp[d];

    sgam[d] = ong[d];
    sbet[d] = onb[d];
    for (int i = d; i < kCH * kXPK; i += 768)
        sdt[i] = dtbc[tokbase * kXPK + i];
    __syncthreads();

    float h = h0[(size_t)blockIdx.x * kDI + d];

    for (int t0 = 0; t0 < kCH; t0 += kTT) {
        // ---- Phase A: barrier-free scan of kTT tokens, y -> smem ----
#pragma unroll 4
        for (int tt = 0; tt < kTT; tt++) {
            const int t = t0 + tt;
            float z = bias;
#pragma unroll
            for (int j = 0; j < kDTR; j++) z = fmaf(sdt[t * kXPK + j], wreg[j], z);
            float av, dtv;
            dt_math(z, Ad, av, dtv);
            const float uv = u[(tokbase + t) * kDI + d];
            h = fmaf(av, h, dtv * sdt[t * kXPK + kDTR] * uv);
            sy[tt * kDI + d] = fmaf(h, sdt[t * kXPK + kDTR + 1], uv * Dd);
        }
        __syncthreads();

        // ---- Phase B: warp-per-token LN + gate (no block barriers) ----
        for (int tok = warp; tok < kTT; tok += 24) {
            float vals[kDI / 32];
            float s1 = 0.f, s2 = 0.f;
#pragma unroll
            for (int j = 0; j < kDI / 32; j++) {
                const float v = sy[tok * kDI + lane + 32 * j];
                vals[j] = v; s1 += v; s2 += v * v;
            }
#pragma unroll
            for (int o = 16; o; o >>= 1) {
                s1 += __shfl_xor_sync(0xffffffffu, s1, o);
                s2 += __shfl_xor_sync(0xffffffffu, s2, o);
            }
            const float mu  = s1 * (1.f / kDI);
            const float var = s2 * (1.f / kDI) - mu * mu;
            const float inv = rsqrtf(var + 1e-5f);
            const int t = t0 + tok;
            const size_t zrow = (tokbase + t) * (2 * (size_t)kDI) + kDI;
            const size_t grow = (tokbase + t) * (size_t)kDI;
#pragma unroll
            for (int j = 0; j < kDI / 32; j++) {
                const int ch = lane + 32 * j;
                const float o  = (vals[j] - mu) * inv * sgam[ch] + sbet[ch];
                const float zv = xz[zrow + ch];
                gate[grow + ch] = __float2bfloat16_rn(o * siluf(zv));
            }
        }
        __syncthreads();
    }
}

// ---------------------------------------------------------------------------
// Launch
// ---------------------------------------------------------------------------
extern "C" void kernel_launch(void* const* d_in, const int* in_sizes, int n_in,
                              void* d_out, int out_size)
{
    const float* x         = (const float*)d_in[0];
    const float* ln1_g     = (const float*)d_in[1];
    const float* ln1_b     = (const float*)d_in[2];
    const float* w_in      = (const float*)d_in[3];
    const float* conv_w    = (const float*)d_in[4];
    const float* x_proj_w  = (const float*)d_in[5];
    const float* dt_proj_w = (const float*)d_in[6];
    const float* dt_proj_b = (const float*)d_in[7];
    const float* A_log     = (const float*)d_in[8];
    const float* Dp        = (const float*)d_in[9];
    const float* outnorm_g = (const float*)d_in[10];
    const float* outnorm_b = (const float*)d_in[11];
    const float* w_out     = (const float*)d_in[12];
    const float* ln2_g     = (const float*)d_in[13];
    const float* ln2_b     = (const float*)d_in[14];
    const float* fc1_w     = (const float*)d_in[15];
    const float* fc1_b     = (const float*)d_in[16];
    const float* fc2_w     = (const float*)d_in[17];
    const float* fc2_b     = (const float*)d_in[18];
    float* out = (float*)d_out;

    float *xz, *u, *dtbc, *xres, *Pp, *Qq, *h0;
    __nv_bfloat16 *h1, *gate, *h2, *hid;
    __nv_bfloat16 *wt_in, *wt_out, *wt_f1, *wt_f2;
    cudaGetSymbolAddress((void**)&h1,    g_h1);
    cudaGetSymbolAddress((void**)&xz,    g_xz);
    cudaGetSymbolAddress((void**)&u,     g_u);
    cudaGetSymbolAddress((void**)&dtbc,  g_dtbc);
    cudaGetSymbolAddress((void**)&gate,  g_gate);
    cudaGetSymbolAddress((void**)&xres,  g_xres);
    cudaGetSymbolAddress((void**)&h2,    g_h2);
    cudaGetSymbolAddress((void**)&hid,   g_hid);
    cudaGetSymbolAddress((void**)&Pp,    g_P);
    cudaGetSymbolAddress((void**)&Qq,    g_Q);
    cudaGetSymbolAddress((void**)&h0,    g_h0);
    cudaGetSymbolAddress((void**)&wt_in, g_wt_in);
    cudaGetSymbolAddress((void**)&wt_out,g_wt_out);
    cudaGetSymbolAddress((void**)&wt_f1, g_wt_f1);
    cudaGetSymbolAddress((void**)&wt_f2, g_wt_f2);

    // GEMM dynamic smem (bytes): DEPTH(3) * (BM+BN) rows * BKP(72) * 2B
    const int SMEM128 = 3 * (128 + 128) * 72 * 2;   // 110592
    const int SMEM64  = 3 * (64 + 128)  * 72 * 2;   // 82944
    cudaFuncSetAttribute((void*)mma_gemm<0, 128, 128>, cudaFuncAttributeMaxDynamicSharedMemorySize, SMEM128);
    cudaFuncSetAttribute((void*)mma_gemm<2, 128, 128>, cudaFuncAttributeMaxDynamicSharedMemorySize, SMEM128);
    cudaFuncSetAttribute((void*)mma_gemm<1, 64, 128>,  cudaFuncAttributeMaxDynamicSharedMemorySize, SMEM64);
    cudaFuncSetAttribute((void*)mma_gemm<3, 64, 128>,  cudaFuncAttributeMaxDynamicSharedMemorySize, SMEM64);

    // pass-3 smem: y tile + dtbc chunk + gamma/beta
    const int SMEM_SCAN = (kTT * kDI + kCH * kXPK + 2 * kDI) * 4;   // 117760 B
    cudaFuncSetAttribute((void*)scan_apply_ln_kernel,
                         cudaFuncAttributeMaxDynamicSharedMemorySize, SMEM_SCAN);

    // 0) transpose all weights -> bf16 [N,K] (one launch)
    transpose_all_kernel<<<2016, dim3(32, 8)>>>(w_in, w_out, fc1_w, fc2_w,
                                                wt_in, wt_out, wt_f1, wt_f2);

    // 1) h1 = bf16(LN(x))
    ln_kernel<kC, 128><<<kNTOK, 128>>>(x, ln1_g, ln1_b, h1, 1e-6f);

    // 2) xz = h1 @ w_in   (N=1536, fp32 out)
    mma_gemm<0, 128, 128><<<dim3((2 * kDI) / 128, kNTOK / 128), 256, SMEM128>>>(
        h1, wt_in, xz, kNTOK, 2 * kDI, kC, nullptr, nullptr);

    // 3) u = silu(dwconv3x3(xm))   (fp32)
    conv_silu_kernel<<<((kNTOK / 4) * (kDI / 4) + 255) / 256, 256>>>(xz, conv_w, u);

    // 4) dtbc = u @ x_proj_w   (fp32)
    xproj_kernel<<<kNTOK / 64, 256>>>(u, x_proj_w, dtbc);

    // 5) chunked selective scan; pass 3 fuses LN+gate via smem y-tile
    scan_chunk_kernel<<<dim3(kB * kNCH, kDI / 256), 256>>>(
        dtbc, dt_proj_w, dt_proj_b, A_log, u, Pp, Qq);
    scan_prefix_kernel<<<(kB * kDI) / 256, 256>>>(Pp, Qq, h0);
    scan_apply_ln_kernel<<<kB * kNCH, 768, SMEM_SCAN>>>(
        dtbc, dt_proj_w, dt_proj_b, A_log, u, Dp, h0, xz,
        outnorm_g, outnorm_b, gate);

    // 6) xres = gate @ w_out + x   (N=384, BM=64, fp32 out)
    mma_gemm<1, 64, 128><<<dim3(kC / 128, kNTOK / 64), 256, SMEM64>>>(
        gate, wt_out, xres, kNTOK, kC, kDI, nullptr, x);

    // 7) h2 = bf16(LN(xres))
    ln_kernel<kC, 128><<<kNTOK, 128>>>(xres, ln2_g, ln2_b, h2, 1e-6f);

    // 8) hid = bf16(gelu(h2 @ fc1_w + fc1_b))   (N=1536)
    mma_gemm<2, 128, 128><<<dim3(kHID / 128, kNTOK / 128), 256, SMEM128>>>(
        h2, wt_f1, hid, kNTOK, kHID, kC, fc1_b, nullptr);

    // 9) out = hid @ fc2_w + fc2_b + xres   (N=384, BM=64, fp32 out)
    mma_gemm<3, 64, 128><<<dim3(kC / 128, kNTOK / 64), 256, SMEM64>>>(
        hid, wt_f2, out, kNTOK, kC, kHID, fc2_b, xres);
}

// round 15
// speedup vs baseline: 1.2633x; 1.0175x over previous
#include <cuda_runtime.h>
#include <cuda_bf16.h>
#include <math.h>
#include <stdint.h>

// ---------------------------------------------------------------------------
// Problem constants
// ---------------------------------------------------------------------------
constexpr int kB     = 16;
constexpr int kH     = 32;
constexpr int kW     = 32;
constexpr int kC     = 384;
constexpr int kDI    = 768;
constexpr int kDTR   = 24;
constexpr int kHID   = 1536;
constexpr int kL     = kH * kW;          // 1024
constexpr int kNTOK  = kB * kL;          // 16384
constexpr int kXPK   = kDTR + 2;         // 26
constexpr int kCH    = 128;              // scan chunk length
constexpr int kNCH   = kL / kCH;         // 8 chunks per sequence
constexpr int kTT    = 32;               // pass-3 token tile (smem-resident y)

// ---------------------------------------------------------------------------
// Scratch
// ---------------------------------------------------------------------------
__device__ __nv_bfloat16 g_h1  [(size_t)kNTOK * kC];      // bf16 GEMM inputs
__device__ __nv_bfloat16 g_gate[(size_t)kNTOK * kDI];
__device__ __nv_bfloat16 g_h2  [(size_t)kNTOK * kC];
__device__ __nv_bfloat16 g_hid [(size_t)kNTOK * kHID];
__device__ float g_xz  [(size_t)kNTOK * 2 * kDI];
__device__ float g_u   [(size_t)kNTOK * kDI];
__device__ float g_dtbc[(size_t)kNTOK * kXPK];
__device__ float g_xres[(size_t)kNTOK * kC];
// chunked-scan state
__device__ float g_P  [(size_t)kB * kNCH * kDI];
__device__ float g_Q  [(size_t)kB * kNCH * kDI];
__device__ float g_h0 [(size_t)kB * kNCH * kDI];
// transposed weights ([N,K], bf16)
__device__ __nv_bfloat16 g_wt_in [(size_t)(2 * kDI) * kC];
__device__ __nv_bfloat16 g_wt_out[(size_t)kC * kDI];
__device__ __nv_bfloat16 g_wt_f1 [(size_t)kHID * kC];
__device__ __nv_bfloat16 g_wt_f2 [(size_t)kC * kHID];

// ---------------------------------------------------------------------------
// Math helpers
// ---------------------------------------------------------------------------
__device__ __forceinline__ float siluf(float x) {
    return __fdividef(x, 1.f + __expf(-x));
}
__device__ __forceinline__ float gelu_tanh(float x) {
    float x3 = x * x * x;
    float targ = 0.7978845608028654f * (x + 0.044715f * x3);
    float th;
    asm("tanh.approx.f32 %0, %1;" : "=f"(th) : "f"(targ));
    return 0.5f * x * (1.f + th);
}

// ---------------------------------------------------------------------------
// PTX helpers (sm_80-safe: cp.async + mma.sync + ldmatrix)
// ---------------------------------------------------------------------------
__device__ __forceinline__ uint32_t smem_to_u32(const void* p) {
    uint32_t a;
    asm("{ .reg .u64 t; cvta.to.shared.u64 t, %1; cvt.u32.u64 %0, t; }" : "=r"(a) : "l"(p));
    return a;
}
__device__ __forceinline__ void cp_async16(uint32_t sa, const void* g) {
    asm volatile("cp.async.cg.shared.global [%0], [%1], 16;" :: "r"(sa), "l"(g));
}
__device__ __forceinline__ void cp_commit() { asm volatile("cp.async.commit_group;" ::: "memory"); }
template <int N>
__device__ __forceinline__ void cp_wait() { asm volatile("cp.async.wait_group %0;" :: "n"(N) : "memory"); }

__device__ __forceinline__ void ldsm_x4(uint32_t& r0, uint32_t& r1, uint32_t& r2,
                                        uint32_t& r3, uint32_t addr) {
    asm volatile("ldmatrix.sync.aligned.m8n8.x4.shared.b16 {%0,%1,%2,%3}, [%4];"
                 : "=r"(r0), "=r"(r1), "=r"(r2), "=r"(r3) : "r"(addr));
}
__device__ __forceinline__ void mma_bf16(float* c, const uint32_t* a, const uint32_t* b) {
    asm volatile(
        "mma.sync.aligned.m16n8k16.row.col.f32.bf16.bf16.f32 "
        "{%0,%1,%2,%3}, {%4,%5,%6,%7}, {%8,%9}, {%0,%1,%2,%3};"
        : "+f"(c[0]), "+f"(c[1]), "+f"(c[2]), "+f"(c[3])
        : "r"(a[0]), "r"(a[1]), "r"(a[2]), "r"(a[3]), "r"(b[0]), "r"(b[1]));
}

// ---------------------------------------------------------------------------
// bf16 mma.sync GEMM: C[M,N] = A[M,K] @ Bt[N,K]^T  (+ fused epilogue)
//   EPI: 0=store f32  1=+resid f32  2=+bias->gelu->bf16  3=+bias+resid f32
//   BM in {128,64}, BN=128, BK=64 (bf16), BKP=72, DEPTH=3, 256 threads.
// ---------------------------------------------------------------------------
template <int EPI, int BM, int BN>
__global__ __launch_bounds__(256, 2) void mma_gemm(
    const __nv_bfloat16* __restrict__ A, const __nv_bfloat16* __restrict__ Bt,
    void* __restrict__ Cv, int M, int N, int K,
    const float* __restrict__ bias, const float* __restrict__ resid)
{
    constexpr int BK = 64, BKP = 72, DEPTH = 3;      // elements (bf16)
    constexpr int MI = BM / 32;
    constexpr int NJ = BN / 32;
    constexpr int WM = BM / 2;
    constexpr int WN = BN / 4;
    constexpr int A_ELEMS = BM * BKP;
    constexpr int B_ELEMS = BN * BKP;
    constexpr int TPR_A = 256 / BM;
    constexpr int SEG_A = 8 / TPR_A;
    constexpr int TPR_B = 256 / BN;
    constexpr int SEG_B = 8 / TPR_B;

    extern __shared__ __nv_bfloat16 smb[];
    __nv_bfloat16* sA = smb;
    __nv_bfloat16* sB = smb + DEPTH * A_ELEMS;
    const uint32_t sAu = smem_to_u32(sA);
    const uint32_t sBu = smem_to_u32(sB);

    const int tid  = threadIdx.x;
    const int wid  = tid >> 5, lane = tid & 31;
    const int grp  = lane >> 2, tg = lane & 3;
    const int m_w  = (wid & 1) * WM;
    const int n_w  = (wid >> 1) * WN;
    const int tile_m = blockIdx.y * BM;
    const int tile_n = blockIdx.x * BN;

    const int nst = K / BK;
    const int ld_row_a = tid / TPR_A;
    const int ld_sb_a  = (tid % TPR_A) * SEG_A;
    const int ld_row_b = tid / TPR_B;
    const int ld_sb_b  = (tid % TPR_B) * SEG_B;

    const int q  = lane >> 3;
    const int rr = lane & 7;
    const uint32_t aoff = (uint32_t)(((m_w + (q & 1) * 8 + rr) * BKP + (q >> 1) * 8) * 2);
    const uint32_t boff = (uint32_t)(((n_w + (q >> 1) * 8 + rr) * BKP + (q & 1) * 8) * 2);

    auto load_stage = [&](int s) {
        const int slot = s % DEPTH;
        const int k0 = s * BK;
        const __nv_bfloat16* ap = A + (size_t)(tile_m + ld_row_a) * K + k0;
        const uint32_t da = sAu + (uint32_t)(slot * A_ELEMS + ld_row_a * BKP) * 2u;
#pragma unroll
        for (int p = 0; p < SEG_A; p++) {
            const int seg = ld_sb_a + p;
            cp_async16(da + (uint32_t)(seg * 16), ap + seg * 8);
        }
        const __nv_bfloat16* bp = Bt + (size_t)(tile_n + ld_row_b) * K + k0;
        const uint32_t db = sBu + (uint32_t)(slot * B_ELEMS + ld_row_b * BKP) * 2u;
#pragma unroll
        for (int p = 0; p < SEG_B; p++) {
            const int seg = ld_sb_b + p;
            cp_async16(db + (uint32_t)(seg * 16), bp + seg * 8);
        }
        cp_commit();
    };

    float acc[MI][NJ][4];
#pragma unroll
    for (int i = 0; i < MI; i++)
#pragma unroll
        for (int j = 0; j < NJ; j++)
#pragma unroll
            for (int r = 0; r < 4; r++) acc[i][j][r] = 0.f;

    const int pre = (nst < DEPTH - 1) ? nst : (DEPTH - 1);
    for (int s = 0; s < pre; s++) load_stage(s);

    for (int s = 0; s < nst; s++) {
        // Tail-aware wait: while loads remain keep DEPTH-2 groups in flight;
        // at intermediate tail stages the needed stage already completed
        // (groups retire in commit order, covered by the prior wait+sync);
        // only the final stage needs a full drain.
        if (s + DEPTH - 1 < nst)  cp_wait<DEPTH - 2>();
        else if (s == nst - 1)    cp_wait<0>();
        __syncthreads();

        const int nxt = s + DEPTH - 1;
        if (nxt < nst) load_stage(nxt);

        const int slot = s % DEPTH;
        const uint32_t aBase = sAu + (uint32_t)(slot * A_ELEMS) * 2u + aoff;
        const uint32_t bBase = sBu + (uint32_t)(slot * B_ELEMS) * 2u + boff;

#pragma unroll
        for (int kk = 0; kk < 4; kk++) {             // 4 x k16 per BK=64
            uint32_t af[MI][4];
#pragma unroll
            for (int i = 0; i < MI; i++)
                ldsm_x4(af[i][0], af[i][1], af[i][2], af[i][3],
                        aBase + (uint32_t)((i * 16 * BKP + kk * 16) * 2));
            uint32_t bf[NJ][2];
#pragma unroll
            for (int jp = 0; jp < NJ / 2; jp++)
                ldsm_x4(bf[2 * jp][0], bf[2 * jp][1], bf[2 * jp + 1][0], bf[2 * jp + 1][1],
                        bBase + (uint32_t)((jp * 16 * BKP + kk * 16) * 2));
#pragma unroll
            for (int i = 0; i < MI; i++)
#pragma unroll
                for (int j = 0; j < NJ; j++)
                    mma_bf16(acc[i][j], af[i], bf[j]);
        }
    }

    // ---- Epilogue ----
    float* Cf = reinterpret_cast<float*>(Cv);
    __nv_bfloat16* Cb = reinterpret_cast<__nv_bfloat16*>(Cv);
#pragma unroll
    for (int i = 0; i < MI; i++) {
        const int rg0 = tile_m + m_w + i * 16 + grp;
#pragma unroll
        for (int j = 0; j < NJ; j++) {
            const int cg = tile_n + n_w + j * 8 + tg * 2;
#pragma unroll
            for (int h = 0; h < 2; h++) {
                const int rg = rg0 + h * 8;
                float2 v = make_float2(acc[i][j][h * 2], acc[i][j][h * 2 + 1]);
                const size_t off = (size_t)rg * N + cg;
                if (EPI == 0) {
                    *reinterpret_cast<float2*>(Cf + off) = v;
                }
                if (EPI == 1) {
                    float2 rr2 = *reinterpret_cast<const float2*>(resid + off);
                    v.x += rr2.x; v.y += rr2.y;
                    *reinterpret_cast<float2*>(Cf + off) = v;
                }
                if (EPI == 2) {
                    float2 bb = *reinterpret_cast<const float2*>(bias + cg);
                    __nv_bfloat162 p;
                    p.x = __float2bfloat16_rn(gelu_tanh(v.x + bb.x));
                    p.y = __float2bfloat16_rn(gelu_tanh(v.y + bb.y));
                    *reinterpret_cast<__nv_bfloat162*>(Cb + off) = p;
                }
                if (EPI == 3) {
                    float2 bb = *reinterpret_cast<const float2*>(bias + cg);
                    float2 rr2 = *reinterpret_cast<const float2*>(resid + off);
                    v.x += bb.x + rr2.x; v.y += bb.y + rr2.y;
                    *reinterpret_cast<float2*>(Cf + off) = v;
                }
            }
        }
    }
}

// ---------------------------------------------------------------------------
// Fused transpose of all 4 weight matrices -> bf16 [N,K]
// ---------------------------------------------------------------------------
__global__ void transpose_all_kernel(
    const float* __restrict__ w_in, const float* __restrict__ w_out,
    const float* __restrict__ fc1,  const float* __restrict__ fc2,
    __nv_bfloat16* __restrict__ o_in, __nv_bfloat16* __restrict__ o_out,
    __nv_bfloat16* __restrict__ o_f1, __nv_bfloat16* __restrict__ o_f2)
{
    __shared__ float t[32][33];
    const int bid = blockIdx.x;
    const float* in; __nv_bfloat16* out; int K, N, tix;
    if (bid < 576)       { in = w_in;  out = o_in;  K = kC;   N = 2 * kDI; tix = bid; }
    else if (bid < 864)  { in = w_out; out = o_out; K = kDI;  N = kC;      tix = bid - 576; }
    else if (bid < 1440) { in = fc1;   out = o_f1;  K = kC;   N = kHID;    tix = bid - 864; }
    else                 { in = fc2;   out = o_f2;  K = kHID; N = kC;      tix = bid - 1440; }
    const int ntx = N / 32;
    const int n0 = (tix % ntx) * 32, k0 = (tix / ntx) * 32;
    const int x = threadIdx.x, y = threadIdx.y;
#pragma unroll
    for (int i = y; i < 32; i += 8)
        t[i][x] = in[(size_t)(k0 + i) * N + n0 + x];
    __syncthreads();
#pragma unroll
    for (int i = y; i < 32; i += 8)
        out[(size_t)(n0 + i) * K + k0 + x] = __float2bfloat16_rn(t[x][i]);
}

// ---------------------------------------------------------------------------
// LayerNorm -> bf16 (used for h1, h2)
// ---------------------------------------------------------------------------
template <int CH, int TPB>
__global__ __launch_bounds__(TPB) void ln_kernel(
    const float* __restrict__ in,
    const float* __restrict__ gam, const float* __restrict__ bet,
    __nv_bfloat16* __restrict__ out, float eps)
{
    constexpr int PER = CH / TPB;
    const int n = blockIdx.x;
    const float* row = in + (size_t)n * CH;

    float v[PER];
    float s = 0.f, s2 = 0.f;
#pragma unroll
    for (int i = 0; i < PER; i++) {
        float t = row[i * TPB + threadIdx.x];
        v[i] = t; s += t; s2 += t * t;
    }
    __shared__ float sm[2 * (TPB / 32)];
#pragma unroll
    for (int o = 16; o; o >>= 1) {
        s  += __shfl_down_sync(0xffffffffu, s,  o);
        s2 += __shfl_down_sync(0xffffffffu, s2, o);
    }
    const int wid = threadIdx.x >> 5, lid = threadIdx.x & 31;
    if (lid == 0) { sm[wid] = s; sm[TPB / 32 + wid] = s2; }
    __syncthreads();
    if (threadIdx.x == 0) {
        float a = 0.f, b = 0.f;
#pragma unroll
        for (int i = 0; i < TPB / 32; i++) { a += sm[i]; b += sm[TPB / 32 + i]; }
        sm[0] = a; sm[1] = b;
    }
    __syncthreads();
    const float mu  = sm[0] * (1.f / CH);
    const float var = sm[1] * (1.f / CH) - mu * mu;
    const float inv = rsqrtf(var + eps);
#pragma unroll
    for (int i = 0; i < PER; i++) {
        const int c = i * TPB + threadIdx.x;
        float o = (v[i] - mu) * inv * gam[c] + bet[c];
        out[(size_t)n * CH + c] = __float2bfloat16_rn(o);
    }
}

// ---------------------------------------------------------------------------
// Depthwise 3x3 SAME conv + silu.
//   Each thread: 2 h-rows x 4 w-positions x 4 channels (float4).
//   24 neighbor loads for 8 outputs (3.0 loads/output vs 4.5 before).
// ---------------------------------------------------------------------------
__global__ __launch_bounds__(256) void conv_silu_kernel(
    const float* __restrict__ xz, const float* __restrict__ cw,
    float* __restrict__ u)
{
    constexpr int D4 = kDI / 4;   // 192
    __shared__ float4 scwv[9 * D4];
    for (int i = threadIdx.x; i < 9 * D4; i += 256) {
        const int k = i / D4, d4 = i % D4;
        scwv[i] = make_float4(cw[(d4 * 4 + 0) * 9 + k], cw[(d4 * 4 + 1) * 9 + k],
                              cw[(d4 * 4 + 2) * 9 + k], cw[(d4 * 4 + 3) * 9 + k]);
    }
    __syncthreads();

    const int idx = blockIdx.x * 256 + threadIdx.x;   // over (kNTOK/8) * D4
    if (idx >= (kNTOK / 8) * D4) return;
    const int d4 = idx % D4;
    const int q  = idx / D4;
    const int wg = q & 7;            // kW/4 = 8 w-groups
    const int hp = (q >> 3) & 15;    // kH/2 = 16 h-pairs
    const int b  = q >> 7;
    const int w0 = wg * 4;
    const int h0 = hp * 2;
    const int nbase = (b * kH + h0) * kW + w0;

    float4 wv[9];
#pragma unroll
    for (int k = 0; k < 9; k++) wv[k] = scwv[k * D4 + d4];

    float4 acc[2][4];
#pragma unroll
    for (int oh = 0; oh < 2; oh++)
#pragma unroll
        for (int t = 0; t < 4; t++) acc[oh][t] = make_float4(0.f, 0.f, 0.f, 0.f);

#pragma unroll
    for (int r = 0; r < 4; r++) {                 // input rows h0-1 .. h0+2
        const int hh = h0 - 1 + r;
        if (hh < 0 || hh >= kH) continue;
        const int rowtok = nbase + (r - 1) * kW;
#pragma unroll
        for (int c = -1; c <= 4; c++) {
            const int ww = w0 + c;
            if (ww < 0 || ww >= kW) continue;
            const float4 v = *reinterpret_cast<const float4*>(
                xz + (size_t)(rowtok + c) * (2 * kDI) + d4 * 4);
#pragma unroll
            for (int oh = 0; oh < 2; oh++) {
                const int ky = r - oh;            // in [0,2] to contribute
                if (ky < 0 || ky > 2) continue;
#pragma unroll
                for (int t = 0; t < 4; t++) {
                    const int kx = c - t + 1;
                    if (kx < 0 || kx > 2) continue;
                    const float4 w9 = wv[ky * 3 + kx];
                    acc[oh][t].x = fmaf(w9.x, v.x, acc[oh][t].x);
                    acc[oh][t].y = fmaf(w9.y, v.y, acc[oh][t].y);
                    acc[oh][t].z = fmaf(w9.z, v.z, acc[oh][t].z);
                    acc[oh][t].w = fmaf(w9.w, v.w, acc[oh][t].w);
                }
            }
        }
    }
#pragma unroll
    for (int oh = 0; oh < 2; oh++)
#pragma unroll
        for (int t = 0; t < 4; t++) {
            float4 o = make_float4(siluf(acc[oh][t].x), siluf(acc[oh][t].y),
                                   siluf(acc[oh][t].z), siluf(acc[oh][t].w));
            *reinterpret_cast<float4*>(
                u + (size_t)(nbase + oh * kW + t) * kDI + d4 * 4) = o;
        }
}

// ---------------------------------------------------------------------------
// x_proj (768 -> 26): 64 tokens per block, 8 tokens per warp (jj-outer)
// ---------------------------------------------------------------------------
__global__ __launch_bounds__(256) void xproj_kernel(
    const float* __restrict__ u, const float* __restrict__ W,
    float* __restrict__ out)
{
    __shared__ float sW[64 * kXPK];
    __shared__ float su[64][65];
    const int warp = threadIdx.x >> 5, lane = threadIdx.x & 31;
    const int nb = blockIdx.x * 64;
    const int tok0 = warp * 8;
    float acc[8] = {0.f, 0.f, 0.f, 0.f, 0.f, 0.f, 0.f, 0.f};

    for (int j0 = 0; j0 < kDI; j0 += 64) {
        for (int i = threadIdx.x; i < 64 * kXPK; i += 256)
            sW[i] = W[j0 * kXPK + i];
        for (int i = threadIdx.x; i < 64 * 64; i += 256) {
            const int r = i >> 6, col = i & 63;
            su[r][col] = u[(size_t)(nb + r) * kDI + j0 + col];
        }
        __syncthreads();

        if (lane < kXPK) {
#pragma unroll 8
            for (int jj = 0; jj < 64; jj++) {
                const float wv = sW[jj * kXPK + lane];
#pragma unroll
                for (int t = 0; t < 8; t++)
                    acc[t] = fmaf(su[tok0 + t][jj], wv, acc[t]);
            }
        }
        __syncthreads();
    }
    if (lane < kXPK) {
#pragma unroll
        for (int t = 0; t < 8; t++)
            out[(size_t)(nb + tok0 + t) * kXPK + lane] = acc[t];
    }
}

// ---------------------------------------------------------------------------
// Chunked selective scan with fused dt_proj (DS=1)
// ---------------------------------------------------------------------------
__device__ __forceinline__ void dt_math(float z, float Ad, float& av, float& dtv) {
    constexpr float L2E = 1.4426950408889634f;
    constexpr float LN2 = 0.6931471805599453f;
    float l;
    if (z > 15.f) l = z * L2E;
    else          l = __log2f(1.f + exp2f(z * L2E));
    dtv = l * LN2;
    av  = exp2f(Ad * l);
}

// Pass 1: per-(b,chunk,d): P = prod(a), Q = chunk scan from h=0
__global__ __launch_bounds__(256) void scan_chunk_kernel(
    const float* __restrict__ dtbc, const float* __restrict__ dtw,
    const float* __restrict__ dtb,  const float* __restrict__ A_log,
    const float* __restrict__ u,
    float* __restrict__ Pp, float* __restrict__ Qq)
{
    __shared__ float sdt[kCH][kXPK];
    const int d = blockIdx.y * 256 + threadIdx.x;
    const int b = blockIdx.x >> 3;
    const int c = blockIdx.x & 7;
    const size_t tokbase = (size_t)b * kL + c * kCH;

    float wreg[kDTR];
#pragma unroll
    for (int j = 0; j < kDTR; j++) wreg[j] = dtw[j * kDI + d];
    const float bias = dtb[d];
    const float Ad   = -__expf(A_log[d]);

    for (int i = threadIdx.x; i < kCH * kXPK; i += 256)
        sdt[i / kXPK][i % kXPK] = dtbc[tokbase * kXPK + i];
    __syncthreads();

    float P = 1.f, Q = 0.f;
#pragma unroll 4
    for (int t = 0; t < kCH; t++) {
        float z = bias;
#pragma unroll
        for (int j = 0; j < kDTR; j++) z = fmaf(sdt[t][j], wreg[j], z);
        float av, dtv;
        dt_math(z, Ad, av, dtv);
        const float buv = dtv * sdt[t][kDTR] * u[(tokbase + t) * kDI + d];
        P *= av;
        Q = fmaf(av, Q, buv);
    }
    const size_t o = (size_t)blockIdx.x * kDI + d;
    Pp[o] = P;
    Qq[o] = Q;
}

// Pass 2: serial prefix over the 8 chunk summaries -> h0 per (b,c,d)
__global__ __launch_bounds__(256) void scan_prefix_kernel(
    const float* __restrict__ Pp, const float* __restrict__ Qq,
    float* __restrict__ h0)
{
    const int idx = blockIdx.x * 256 + threadIdx.x;   // b*kDI + d
    const int b = idx / kDI, d = idx % kDI;
    float h = 0.f;
#pragma unroll
    for (int c = 0; c < kNCH; c++) {
        const size_t o = (size_t)(b * kNCH + c) * kDI + d;
        h0[o] = h;
        h = fmaf(Pp[o], h, Qq[o]);
    }
}

// Pass 3 (FUSED, tiled): scan 32 tokens barrier-free into an smem y-tile,
// then warp-per-token LN + silu(z) gate -> bf16.
// ---------------------------------------------------------------------------
__global__ __launch_bounds__(768, 1) void scan_apply_ln_kernel(
    const float* __restrict__ dtbc, const float* __restrict__ dtw,
    const float* __restrict__ dtb,  const float* __restrict__ A_log,
    const float* __restrict__ u,    const float* __restrict__ Dp,
    const float* __restrict__ h0,   const float* __restrict__ xz,
    const float* __restrict__ ong,  const float* __restrict__ onb,
    __nv_bfloat16* __restrict__ gate)
{
    extern __shared__ float smf[];
    float* sy   = smf;                      // [kTT][kDI]
    float* sdt  = smf + kTT * kDI;          // [kCH][kXPK]
    float* sgam = sdt + kCH * kXPK;         // [kDI]
    float* sbet = sgam + kDI;               // [kDI]

    const int d = threadIdx.x;              // 0..767
    const int b = blockIdx.x >> 3;
    const int c = blockIdx.x & 7;
    const size_t tokbase = (size_t)b * kL + c * kCH;
    const int warp = d >> 5, lane = d & 31;

    float wreg[kDTR];
#pragma unroll
    for (int j = 0; j < kDTR; j++) wreg[j] = dtw[j * kDI + d];
    const float bias = dtb[d];
    const float Ad   = -__expf(A_log[d]);
    const float Dd   = Dp[d];

    sgam[d] = ong[d];
    sbet[d] = onb[d];
    for (int i = d; i < kCH * kXPK; i += 768)
        sdt[i] = dtbc[tokbase * kXPK + i];
    __syncthreads();

    float h = h0[(size_t)blockIdx.x * kDI + d];

    for (int t0 = 0; t0 < kCH; t0 += kTT) {
        // ---- Phase A: barrier-free scan of kTT tokens, y -> smem ----
#pragma unroll 4
        for (int tt = 0; tt < kTT; tt++) {
            const int t = t0 + tt;
            float z = bias;
#pragma unroll
            for (int j = 0; j < kDTR; j++) z = fmaf(sdt[t * kXPK + j], wreg[j], z);
            float av, dtv;
            dt_math(z, Ad, av, dtv);
            const float uv = u[(tokbase + t) * kDI + d];
            h = fmaf(av, h, dtv * sdt[t * kXPK + kDTR] * uv);
            sy[tt * kDI + d] = fmaf(h, sdt[t * kXPK + kDTR + 1], uv * Dd);
        }
        __syncthreads();

        // ---- Phase B: warp-per-token LN + gate (no block barriers) ----
        for (int tok = warp; tok < kTT; tok += 24) {
            float vals[kDI / 32];
            float s1 = 0.f, s2 = 0.f;
#pragma unroll
            for (int j = 0; j < kDI / 32; j++) {
                const float v = sy[tok * kDI + lane + 32 * j];
                vals[j] = v; s1 += v; s2 += v * v;
            }
#pragma unroll
            for (int o = 16; o; o >>= 1) {
                s1 += __shfl_xor_sync(0xffffffffu, s1, o);
                s2 += __shfl_xor_sync(0xffffffffu, s2, o);
            }
            const float mu  = s1 * (1.f / kDI);
            const float var = s2 * (1.f / kDI) - mu * mu;
            const float inv = rsqrtf(var + 1e-5f);
            const int t = t0 + tok;
            const size_t zrow = (tokbase + t) * (2 * (size_t)kDI) + kDI;
            const size_t grow = (tokbase + t) * (size_t)kDI;
#pragma unroll
            for (int j = 0; j < kDI / 32; j++) {
                const int ch = lane + 32 * j;
                const float o  = (vals[j] - mu) * inv * sgam[ch] + sbet[ch];
                const float zv = xz[zrow + ch];
                gate[grow + ch] = __float2bfloat16_rn(o * siluf(zv));
            }
        }
        __syncthreads();
    }
}

// ---------------------------------------------------------------------------
// Launch
// ---------------------------------------------------------------------------
extern "C" void kernel_launch(void* const* d_in, const int* in_sizes, int n_in,
                              void* d_out, int out_size)
{
    const float* x         = (const float*)d_in[0];
    const float* ln1_g     = (const float*)d_in[1];
    const float* ln1_b     = (const float*)d_in[2];
    const float* w_in      = (const float*)d_in[3];
    const float* conv_w    = (const float*)d_in[4];
    const float* x_proj_w  = (const float*)d_in[5];
    const float* dt_proj_w = (const float*)d_in[6];
    const float* dt_proj_b = (const float*)d_in[7];
    const float* A_log     = (const float*)d_in[8];
    const float* Dp        = (const float*)d_in[9];
    const float* outnorm_g = (const float*)d_in[10];
    const float* outnorm_b = (const float*)d_in[11];
    const float* w_out     = (const float*)d_in[12];
    const float* ln2_g     = (const float*)d_in[13];
    const float* ln2_b     = (const float*)d_in[14];
    const float* fc1_w     = (const float*)d_in[15];
    const float* fc1_b     = (const float*)d_in[16];
    const float* fc2_w     = (const float*)d_in[17];
    const float* fc2_b     = (const float*)d_in[18];
    float* out = (float*)d_out;

    float *xz, *u, *dtbc, *xres, *Pp, *Qq, *h0;
    __nv_bfloat16 *h1, *gate, *h2, *hid;
    __nv_bfloat16 *wt_in, *wt_out, *wt_f1, *wt_f2;
    cudaGetSymbolAddress((void**)&h1,    g_h1);
    cudaGetSymbolAddress((void**)&xz,    g_xz);
    cudaGetSymbolAddress((void**)&u,     g_u);
    cudaGetSymbolAddress((void**)&dtbc,  g_dtbc);
    cudaGetSymbolAddress((void**)&gate,  g_gate);
    cudaGetSymbolAddress((void**)&xres,  g_xres);
    cudaGetSymbolAddress((void**)&h2,    g_h2);
    cudaGetSymbolAddress((void**)&hid,   g_hid);
    cudaGetSymbolAddress((void**)&Pp,    g_P);
    cudaGetSymbolAddress((void**)&Qq,    g_Q);
    cudaGetSymbolAddress((void**)&h0,    g_h0);
    cudaGetSymbolAddress((void**)&wt_in, g_wt_in);
    cudaGetSymbolAddress((void**)&wt_out,g_wt_out);
    cudaGetSymbolAddress((void**)&wt_f1, g_wt_f1);
    cudaGetSymbolAddress((void**)&wt_f2, g_wt_f2);

    // GEMM dynamic smem (bytes): DEPTH(3) * (BM+BN) rows * BKP(72) * 2B
    const int SMEM128 = 3 * (128 + 128) * 72 * 2;   // 110592
    const int SMEM64  = 3 * (64 + 128)  * 72 * 2;   // 82944
    cudaFuncSetAttribute((void*)mma_gemm<0, 128, 128>, cudaFuncAttributeMaxDynamicSharedMemorySize, SMEM128);
    cudaFuncSetAttribute((void*)mma_gemm<2, 128, 128>, cudaFuncAttributeMaxDynamicSharedMemorySize, SMEM128);
    cudaFuncSetAttribute((void*)mma_gemm<1, 64, 128>,  cudaFuncAttributeMaxDynamicSharedMemorySize, SMEM64);
    cudaFuncSetAttribute((void*)mma_gemm<3, 64, 128>,  cudaFuncAttributeMaxDynamicSharedMemorySize, SMEM64);

    // pass-3 smem: y tile + dtbc chunk + gamma/beta
    const int SMEM_SCAN = (kTT * kDI + kCH * kXPK + 2 * kDI) * 4;   // 117760 B
    cudaFuncSetAttribute((void*)scan_apply_ln_kernel,
                         cudaFuncAttributeMaxDynamicSharedMemorySize, SMEM_SCAN);

    // 0) transpose all weights -> bf16 [N,K] (one launch)
    transpose_all_kernel<<<2016, dim3(32, 8)>>>(w_in, w_out, fc1_w, fc2_w,
                                                wt_in, wt_out, wt_f1, wt_f2);

    // 1) h1 = bf16(LN(x))
    ln_kernel<kC, 128><<<kNTOK, 128>>>(x, ln1_g, ln1_b, h1, 1e-6f);

    // 2) xz = h1 @ w_in   (N=1536, fp32 out)
    mma_gemm<0, 128, 128><<<dim3((2 * kDI) / 128, kNTOK / 128), 256, SMEM128>>>(
        h1, wt_in, xz, kNTOK, 2 * kDI, kC, nullptr, nullptr);

    // 3) u = silu(dwconv3x3(xm))   (fp32)
    conv_silu_kernel<<<((kNTOK / 8) * (kDI / 4) + 255) / 256, 256>>>(xz, conv_w, u);

    // 4) dtbc = u @ x_proj_w   (fp32)
    xproj_kernel<<<kNTOK / 64, 256>>>(u, x_proj_w, dtbc);

    // 5) chunked selective scan; pass 3 fuses LN+gate via smem y-tile
    scan_chunk_kernel<<<dim3(kB * kNCH, kDI / 256), 256>>>(
        dtbc, dt_proj_w, dt_proj_b, A_log, u, Pp, Qq);
    scan_prefix_kernel<<<(kB * kDI) / 256, 256>>>(Pp, Qq, h0);
    scan_apply_ln_kernel<<<kB * kNCH, 768, SMEM_SCAN>>>(
        dtbc, dt_proj_w, dt_proj_b, A_log, u, Dp, h0, xz,
        outnorm_g, outnorm_b, gate);

    // 6) xres = gate @ w_out + x   (N=384, BM=64, fp32 out)
    mma_gemm<1, 64, 128><<<dim3(kC / 128, kNTOK / 64), 256, SMEM64>>>(
        gate, wt_out, xres, kNTOK, kC, kDI, nullptr, x);

    // 7) h2 = bf16(LN(xres))
    ln_kernel<kC, 128><<<kNTOK, 128>>>(xres, ln2_g, ln2_b, h2, 1e-6f);

    // 8) hid = bf16(gelu(h2 @ fc1_w + fc1_b))   (N=1536)
    mma_gemm<2, 128, 128><<<dim3(kHID / 128, kNTOK / 128), 256, SMEM128>>>(
        h2, wt_f1, hid, kNTOK, kHID, kC, fc1_b, nullptr);

    // 9) out = hid @ fc2_w + fc2_b + xres   (N=384, BM=64, fp32 out)
    mma_gemm<3, 64, 128><<<dim3(kC / 128, kNTOK / 64), 256, SMEM64>>>(
        hid, wt_f2, out, kNTOK, kC, kHID, fc2_b, xres);
}